// round 11
// baseline (speedup 1.0000x reference)
#include <cuda_runtime.h>
#include <math.h>

#define BB 4
#define SS 1024
#define DD 1024
#define HH 16
#define HD 64

// ---------------- static scratch (no device allocations allowed) ----------------
__device__ float g_q[BB*HH*SS*HD];     // 16 MB  [B,H,S,HD]
__device__ float g_k[BB*HH*SS*HD];     // 16 MB
__device__ float g_v[BB*HH*SS*HD];     // 16 MB
__device__ float g_ctx[BB*SS*DD];      // 16 MB  [B,S,D]
__device__ float g_bias[BB*HH];

// ---------------- projection GEMM: C[4096,1024] = A @ W + bias ----------------
// BM=BN=128, BK=16, 256 threads, each thread 8x8.
// mode 0/1/2 -> A from arg, write q/k/v in [B,H,S,HD]
// mode 3     -> A = g_ctx (DEVICE-side symbol selection!), write row-major to Cout.
__global__ __launch_bounds__(256) void proj_kernel(
    const float* __restrict__ A, const float* __restrict__ W,
    const float* __restrict__ bias, float* __restrict__ Cout, int mode)
{
    // CRITICAL: device-symbol address must be taken in DEVICE code. Passing g_ctx
    // from host passes the host shadow (which GB300 ATS silently reads as zeros).
    const float* Asrc = (mode == 3) ? (const float*)g_ctx : A;

    __shared__ float As[16][132];
    __shared__ float Bs[16][132];
    const int bx = blockIdx.x;
    const int by = blockIdx.y;
    const int t  = threadIdx.x;
    const int tx = t & 15, ty = t >> 4;
    const int rowBase = by * 128;
    const int colBase = bx * 128;

    float acc[8][8];
    #pragma unroll
    for (int i = 0; i < 8; i++)
        #pragma unroll
        for (int j = 0; j < 8; j++) acc[i][j] = 0.f;

    for (int k0 = 0; k0 < DD; k0 += 16) {
        #pragma unroll
        for (int i = 0; i < 2; i++) {
            int idx = t + i * 256;
            int r   = idx >> 2;
            int kc  = (idx & 3) * 4;
            float4 v = *reinterpret_cast<const float4*>(&Asrc[(size_t)(rowBase + r) * DD + k0 + kc]);
            As[kc + 0][r] = v.x; As[kc + 1][r] = v.y;
            As[kc + 2][r] = v.z; As[kc + 3][r] = v.w;
        }
        #pragma unroll
        for (int i = 0; i < 2; i++) {
            int idx = t + i * 256;
            int kr  = idx >> 5;
            int nc  = (idx & 31) * 4;
            *reinterpret_cast<float4*>(&Bs[kr][nc]) =
                *reinterpret_cast<const float4*>(&W[(size_t)(k0 + kr) * DD + colBase + nc]);
        }
        __syncthreads();
        #pragma unroll
        for (int kk = 0; kk < 16; kk++) {
            float ra[8], rb[8];
            float4 a0 = *reinterpret_cast<float4*>(&As[kk][ty * 8]);
            float4 a1 = *reinterpret_cast<float4*>(&As[kk][ty * 8 + 4]);
            float4 b0 = *reinterpret_cast<float4*>(&Bs[kk][tx * 8]);
            float4 b1 = *reinterpret_cast<float4*>(&Bs[kk][tx * 8 + 4]);
            ra[0]=a0.x; ra[1]=a0.y; ra[2]=a0.z; ra[3]=a0.w;
            ra[4]=a1.x; ra[5]=a1.y; ra[6]=a1.z; ra[7]=a1.w;
            rb[0]=b0.x; rb[1]=b0.y; rb[2]=b0.z; rb[3]=b0.w;
            rb[4]=b1.x; rb[5]=b1.y; rb[6]=b1.z; rb[7]=b1.w;
            #pragma unroll
            for (int i = 0; i < 8; i++)
                #pragma unroll
                for (int j = 0; j < 8; j++)
                    acc[i][j] += ra[i] * rb[j];
        }
        __syncthreads();
    }

    float* dst = (mode == 0) ? g_q : (mode == 1) ? g_k : (mode == 2) ? g_v : Cout;
    #pragma unroll
    for (int i = 0; i < 8; i++) {
        int row = rowBase + ty * 8 + i;
        int b = row >> 10, s = row & 1023;
        #pragma unroll
        for (int j = 0; j < 8; j++) {
            int col = colBase + tx * 8 + j;
            float v = acc[i][j] + bias[col];
            if (mode <= 2) {
                int h = col >> 6, d = col & 63;
                dst[(((size_t)(b * HH + h) * SS + s) * HD) + d] = v;
            } else {
                dst[(size_t)row * DD + col] = v;
            }
        }
    }
}

// ---------------- goal bias: g_bias[b,h] = goal_state[b,:] . Wg[:,h] + bg[h] --------
__global__ void goalbias_kernel(const float* __restrict__ gs,
                                const float* __restrict__ Wg,
                                const float* __restrict__ bg)
{
    int h = blockIdx.x, b = blockIdx.y;
    int t = threadIdx.x; // 256
    float sum = 0.f;
    for (int k = t; k < DD; k += 256)
        sum += gs[b * DD + k] * Wg[k * HH + h];
    __shared__ float red[256];
    red[t] = sum; __syncthreads();
    for (int o = 128; o > 0; o >>= 1) {
        if (t < o) red[t] += red[t + o];
        __syncthreads();
    }
    if (t == 0) g_bias[b * HH + h] = red[0] + bg[h];
}

// ---------------- fused flash attention (two-pass, exact softmax) ----------------
// grid = (qt 0..15, bh 0..63), 256 threads. Dynamic smem: Qs + KV + Ps (3 x 64x68 f32).
// Writes attention probs to attn (if non-null) and context to g_ctx.
__global__ __launch_bounds__(256) void flash_kernel(float* __restrict__ attn)
{
    const int qt = blockIdx.x, bh = blockIdx.y;
    extern __shared__ float sm[];
    float* Qs = sm;               // [d][row]  stride 68
    float* KV = sm + 64 * 68;     // K: [d][col] / V: [k][d], stride 68
    float* Ps = sm + 2 * 64 * 68; // [k][row]  stride 68

    const int t = threadIdx.x;
    const int tx = t & 15, ty = t >> 4;
    const float* Qg = g_q + ((size_t)bh * SS + qt * 64) * HD;
    const float* Kg = g_k + (size_t)bh * SS * HD;
    const float* Vg = g_v + (size_t)bh * SS * HD;
    const float bias = g_bias[bh];
    const float scale = 0.125f; // 1/sqrt(64)

    // load Q tile 64x64 as [d][row]
    #pragma unroll
    for (int i = 0; i < 4; i++) {
        int idx = t + i * 256;
        int r   = idx >> 4;
        int dc  = (idx & 15) * 4;
        float4 v = *reinterpret_cast<const float4*>(&Qg[r * HD + dc]);
        Qs[(dc+0)*68 + r] = v.x; Qs[(dc+1)*68 + r] = v.y;
        Qs[(dc+2)*68 + r] = v.z; Qs[(dc+3)*68 + r] = v.w;
    }

    float M[4], L[4];
    #pragma unroll
    for (int i = 0; i < 4; i++) { M[i] = -1e30f; L[i] = 0.f; }

    // ---------- PASS 1: exact row max + sum ----------
    for (int kt = 0; kt <= qt; kt++) {
        __syncthreads();
        #pragma unroll
        for (int i = 0; i < 4; i++) {
            int idx = t + i * 256;
            int r   = idx >> 4;
            int dc  = (idx & 15) * 4;
            float4 v = *reinterpret_cast<const float4*>(&Kg[(kt * 64 + r) * HD + dc]);
            KV[(dc+0)*68 + r] = v.x; KV[(dc+1)*68 + r] = v.y;
            KV[(dc+2)*68 + r] = v.z; KV[(dc+3)*68 + r] = v.w;
        }
        __syncthreads();

        float s[4][4];
        #pragma unroll
        for (int i = 0; i < 4; i++)
            #pragma unroll
            for (int j = 0; j < 4; j++) s[i][j] = 0.f;
        #pragma unroll 8
        for (int d = 0; d < 64; d++) {
            float4 a = *reinterpret_cast<float4*>(&Qs[d*68 + ty*4]);
            float4 b = *reinterpret_cast<float4*>(&KV[d*68 + tx*4]);
            float ra[4] = {a.x, a.y, a.z, a.w};
            float rb[4] = {b.x, b.y, b.z, b.w};
            #pragma unroll
            for (int i = 0; i < 4; i++)
                #pragma unroll
                for (int j = 0; j < 4; j++)
                    s[i][j] += ra[i] * rb[j];
        }
        #pragma unroll
        for (int i = 0; i < 4; i++) {
            int qrow = qt * 64 + ty * 4 + i;
            #pragma unroll
            for (int j = 0; j < 4; j++) {
                int kcol = kt * 64 + tx * 4 + j;
                float v = s[i][j] * scale + bias;
                s[i][j] = (kcol > qrow) ? -1e30f : v;
            }
            // row reduce across the 16-lane tx group
            float m = fmaxf(fmaxf(s[i][0], s[i][1]), fmaxf(s[i][2], s[i][3]));
            #pragma unroll
            for (int o = 1; o < 16; o <<= 1)
                m = fmaxf(m, __shfl_xor_sync(0xffffffffu, m, o));
            float Mn = fmaxf(M[i], m);
            float l = expf(s[i][0]-Mn) + expf(s[i][1]-Mn) + expf(s[i][2]-Mn) + expf(s[i][3]-Mn);
            #pragma unroll
            for (int o = 1; o < 16; o <<= 1)
                l += __shfl_xor_sync(0xffffffffu, l, o);
            L[i] = L[i] * expf(M[i] - Mn) + l;
            M[i] = Mn;
        }
    }

    float invL[4];
    #pragma unroll
    for (int i = 0; i < 4; i++) invL[i] = 1.0f / L[i];

    // ---------- PASS 2: write probs + accumulate ctx ----------
    float acc[4][4];
    #pragma unroll
    for (int i = 0; i < 4; i++)
        #pragma unroll
        for (int j = 0; j < 4; j++) acc[i][j] = 0.f;

    for (int kt = 0; kt <= qt; kt++) {
        __syncthreads();   // protect KV from previous iteration's readers
        #pragma unroll
        for (int i = 0; i < 4; i++) {
            int idx = t + i * 256;
            int r   = idx >> 4;
            int dc  = (idx & 15) * 4;
            float4 v = *reinterpret_cast<const float4*>(&Kg[(kt * 64 + r) * HD + dc]);
            KV[(dc+0)*68 + r] = v.x; KV[(dc+1)*68 + r] = v.y;
            KV[(dc+2)*68 + r] = v.z; KV[(dc+3)*68 + r] = v.w;
        }
        __syncthreads();

        float s[4][4];
        #pragma unroll
        for (int i = 0; i < 4; i++)
            #pragma unroll
            for (int j = 0; j < 4; j++) s[i][j] = 0.f;
        #pragma unroll 8
        for (int d = 0; d < 64; d++) {
            float4 a = *reinterpret_cast<float4*>(&Qs[d*68 + ty*4]);
            float4 b = *reinterpret_cast<float4*>(&KV[d*68 + tx*4]);
            float ra[4] = {a.x, a.y, a.z, a.w};
            float rb[4] = {b.x, b.y, b.z, b.w};
            #pragma unroll
            for (int i = 0; i < 4; i++)
                #pragma unroll
                for (int j = 0; j < 4; j++)
                    s[i][j] += ra[i] * rb[j];
        }
        float p[4][4];
        #pragma unroll
        for (int i = 0; i < 4; i++) {
            int qrow = qt * 64 + ty * 4 + i;
            #pragma unroll
            for (int j = 0; j < 4; j++) {
                int kcol = kt * 64 + tx * 4 + j;
                float v = s[i][j] * scale + bias;
                v = (kcol > qrow) ? -1e30f : v;
                p[i][j] = expf(v - M[i]) * invL[i];
            }
        }
        if (attn) {
            #pragma unroll
            for (int i = 0; i < 4; i++) {
                float4 pv = make_float4(p[i][0], p[i][1], p[i][2], p[i][3]);
                *reinterpret_cast<float4*>(
                    &attn[(size_t)bh * SS * SS + (size_t)(qt*64 + ty*4 + i) * SS + kt*64 + tx*4]) = pv;
            }
        }
        __syncthreads();   // all threads done reading KV(K)
        #pragma unroll
        for (int i = 0; i < 4; i++)
            #pragma unroll
            for (int j = 0; j < 4; j++)
                Ps[(tx*4+j)*68 + ty*4+i] = p[i][j];
        #pragma unroll
        for (int i = 0; i < 4; i++) {
            int idx = t + i * 256;
            int r   = idx >> 4;
            int dc  = (idx & 15) * 4;
            *reinterpret_cast<float4*>(&KV[r*68 + dc]) =
                *reinterpret_cast<const float4*>(&Vg[(kt * 64 + r) * HD + dc]);
        }
        __syncthreads();
        #pragma unroll 8
        for (int kk = 0; kk < 64; kk++) {
            float4 a = *reinterpret_cast<float4*>(&Ps[kk*68 + ty*4]);
            float4 b = *reinterpret_cast<float4*>(&KV[kk*68 + tx*4]);
            float ra[4] = {a.x, a.y, a.z, a.w};
            float rb[4] = {b.x, b.y, b.z, b.w};
            #pragma unroll
            for (int i = 0; i < 4; i++)
                #pragma unroll
                for (int j = 0; j < 4; j++)
                    acc[i][j] += ra[i] * rb[j];
        }
    }

    // write ctx [B,S,D]
    const int b = bh >> 4, h = bh & 15;
    #pragma unroll
    for (int i = 0; i < 4; i++) {
        int srow = qt * 64 + ty * 4 + i;
        float4 cv = make_float4(acc[i][0], acc[i][1], acc[i][2], acc[i][3]);
        *reinterpret_cast<float4*>(
            &g_ctx[((size_t)(b * SS + srow)) * DD + h * 64 + tx * 4]) = cv;
    }

    // zero the causally-masked upper region of this q-tile's attn rows
    if (attn && qt < 15) {
        const int c0 = (qt + 1) * 64;
        const int w4 = (SS - c0) >> 2;
        const float4 z4 = make_float4(0.f, 0.f, 0.f, 0.f);
        for (int idx = t; idx < 64 * w4; idx += 256) {
            int r = idx / w4, c = idx % w4;
            *reinterpret_cast<float4*>(
                &attn[(size_t)bh * SS * SS + (size_t)(qt*64 + r) * SS + c0 + c*4]) = z4;
        }
    }
}

// ---------------- launch ----------------
extern "C" void kernel_launch(void* const* d_in, const int* in_sizes, int n_in,
                              void* d_out, int out_size)
{
    const float *query, *key, *value, *goal_state;
    const float *Wq, *bq, *Wk, *bk, *Wv, *bv, *Wo, *bo, *Wg, *bg;

    if (in_sizes[0] == DD * HH) {
        // alphabetical ordering: Wg,Wk,Wo,Wq,Wv,attn_mask,bg,bk,bo,bq,bv,goal,key,query,value
        Wg = (const float*)d_in[0];
        Wk = (const float*)d_in[1];
        Wo = (const float*)d_in[2];
        Wq = (const float*)d_in[3];
        Wv = (const float*)d_in[4];
        bg = (const float*)d_in[6];
        bk = (const float*)d_in[7];
        bo = (const float*)d_in[8];
        bq = (const float*)d_in[9];
        bv = (const float*)d_in[10];
        goal_state = (const float*)d_in[11];
        key   = (const float*)d_in[12];
        query = (const float*)d_in[13];
        value = (const float*)d_in[14];
    } else {
        // locate 10-tensor weight block by its size signature
        int wb = -1;
        for (int i = 0; i + 9 < n_in; i++) {
            if (in_sizes[i]     == 1048576 && in_sizes[i + 1] == 1024 &&
                in_sizes[i + 2] == 1048576 && in_sizes[i + 3] == 1024 &&
                in_sizes[i + 4] == 1048576 && in_sizes[i + 5] == 1024 &&
                in_sizes[i + 6] == 1048576 && in_sizes[i + 7] == 1024 &&
                in_sizes[i + 8] == 16384   && in_sizes[i + 9] == 16) {
                wb = i;
                break;
            }
        }
        if (wb < 0) wb = n_in - 10;
        Wq = (const float*)d_in[wb + 0];
        bq = (const float*)d_in[wb + 1];
        Wk = (const float*)d_in[wb + 2];
        bk = (const float*)d_in[wb + 3];
        Wv = (const float*)d_in[wb + 4];
        bv = (const float*)d_in[wb + 5];
        Wo = (const float*)d_in[wb + 6];
        bo = (const float*)d_in[wb + 7];
        Wg = (const float*)d_in[wb + 8];
        bg = (const float*)d_in[wb + 9];

        int qi = -1, ki = -1, vi = -1, gi = -1;
        for (int i = 0; i < n_in; i++) {
            if (i >= wb && i < wb + 10) continue;
            if (in_sizes[i] == BB * SS * DD) {
                if (qi < 0) qi = i;
                else if (ki < 0) ki = i;
                else if (vi < 0) vi = i;
            } else if (in_sizes[i] == BB * DD && gi < 0) {
                gi = i;
            }
        }
        query      = (const float*)d_in[qi < 0 ? 0 : qi];
        key        = (const float*)d_in[ki < 0 ? 1 : ki];
        value      = (const float*)d_in[vi < 0 ? 2 : vi];
        goal_state = (const float*)d_in[gi < 0 ? 3 : gi];
    }

    float* out = (float*)d_out;
    const size_t out_elems  = (size_t)BB * SS * DD;        // 4,194,304
    const size_t attn_elems = (size_t)BB * HH * SS * SS;   // 67,108,864

    // attention weights go into d_out (tuple output) if there is room; otherwise skip.
    float* attn = ((size_t)out_size >= out_elems + attn_elems) ? (out + out_elems) : nullptr;

    dim3 projGrid(DD / 128, (BB * SS) / 128);   // (8, 32)
    proj_kernel<<<projGrid, 256>>>(query, Wq, bq, nullptr, 0);
    proj_kernel<<<projGrid, 256>>>(key,   Wk, bk, nullptr, 1);
    proj_kernel<<<projGrid, 256>>>(value, Wv, bv, nullptr, 2);

    goalbias_kernel<<<dim3(HH, BB), 256>>>(goal_state, Wg, bg);

    const int flash_smem = 3 * 64 * 68 * (int)sizeof(float);  // 52,224 B
    cudaFuncSetAttribute(flash_kernel, cudaFuncAttributeMaxDynamicSharedMemorySize, flash_smem);
    flash_kernel<<<dim3(SS / 64, BB * HH), 256, flash_smem>>>(attn);

    // mode 3: A-source resolved in device code (g_ctx). First arg is a dummy.
    proj_kernel<<<projGrid, 256>>>(out, Wo, bo, out, 3);
}

// round 16
// speedup vs baseline: 1.2784x; 1.2784x over previous
#include <cuda_runtime.h>
#include <cuda_bf16.h>
#include <mma.h>
#include <math.h>
#include <stdint.h>

using namespace nvcuda;

#define BB 4
#define SS 1024
#define DD 1024
#define HH 16
#define HD 64

// ---------------- static scratch ----------------
__device__ float g_q[BB*HH*SS*HD];     // [B,H,S,HD]
__device__ float g_k[BB*HH*SS*HD];
__device__ float g_v[BB*HH*SS*HD];
__device__ float g_ctx[BB*SS*DD];      // [B,S,D]
__device__ float g_bias[BB*HH];

// ============ wmma bf16 split-3 projection GEMM: C[4096,1024] = A @ W + bias ============
// CTA tile 128(M) x 128(N), 8 warps (2x4), warp tile 64x32 (4x2 fragments of 16x16).
// K chunked 32-wide. A and W converted fp32 -> bf16 hi + bf16 lo in smem.
// acc = bias (preloaded) + sum( Ahi*Whi + Ahi*Wlo + Alo*Whi ), fp32 accumulate.
#define KC 32
#define A_STR 40     // bf16 elems per A smem row  (80 B; fragment bases 32B-aligned)
#define B_STR 136    // bf16 elems per B smem row  (272 B)

#define SA_HI  0
#define SA_LO  (SA_HI + 128 * A_STR * 2)   // 10240
#define SB_HI  (SA_LO + 128 * A_STR * 2)   // 20480
#define SB_LO  (SB_HI + KC * B_STR * 2)    // 29184
#define SBIAS  (SB_LO + KC * B_STR * 2)    // 37888
#define SM_TOT (SBIAS + 16 * B_STR * 4)    // 46592 bytes

__device__ __forceinline__ void split2(float x, __nv_bfloat16& hi, __nv_bfloat16& lo) {
    hi = __float2bfloat16_rn(x);
    lo = __float2bfloat16_rn(x - __bfloat162float(hi));
}

__global__ __launch_bounds__(256) void proj_wmma_kernel(
    const float* __restrict__ A, const float* __restrict__ W,
    const float* __restrict__ bias, float* __restrict__ Cout, int mode)
{
    extern __shared__ char smem[];
    __nv_bfloat16* Ahi = (__nv_bfloat16*)(smem + SA_HI);
    __nv_bfloat16* Alo = (__nv_bfloat16*)(smem + SA_LO);
    __nv_bfloat16* Bhi = (__nv_bfloat16*)(smem + SB_HI);
    __nv_bfloat16* Blo = (__nv_bfloat16*)(smem + SB_LO);
    float*        biasC = (float*)(smem + SBIAS);

    // device-side symbol selection (NEVER pass __device__ symbols from host: ATS
    // silently reads the host shadow as zeros on GB300).
    const float* Asrc = (mode == 3) ? (const float*)g_ctx : A;

    const int t = threadIdx.x;
    const int wid = t >> 5;
    const int warp_m = wid >> 2;      // 0..1
    const int warp_n = wid & 3;       // 0..3
    const int n0 = blockIdx.x * 128;
    const int rowBase = blockIdx.y * 128;

    // bias broadcast tile: 16 identical rows of bias[n0..n0+127]
    for (int idx = t; idx < 16 * 128; idx += 256) {
        int r = idx >> 7, c = idx & 127;
        biasC[r * B_STR + c] = bias[n0 + c];
    }
    __syncthreads();

    wmma::fragment<wmma::accumulator, 16, 16, 16, float> acc[4][2];
    #pragma unroll
    for (int i = 0; i < 4; i++)
        #pragma unroll
        for (int j = 0; j < 2; j++)
            wmma::load_matrix_sync(acc[i][j], biasC + warp_n * 32 + j * 16,
                                   B_STR, wmma::mem_row_major);

    for (int k0 = 0; k0 < DD; k0 += KC) {
        __syncthreads();
        // ---- A chunk: 128 rows x 32 k (fp32) -> hi/lo bf16 ----
        #pragma unroll
        for (int i = 0; i < 4; i++) {
            int idx = i * 256 + t;            // 0..1023 float4s
            int r = idx >> 3, c = idx & 7;    // 8 float4 per row
            float4 v = *reinterpret_cast<const float4*>(
                &Asrc[(size_t)(rowBase + r) * DD + k0 + c * 4]);
            __nv_bfloat16 h0,h1,h2,h3,l0,l1,l2,l3;
            split2(v.x,h0,l0); split2(v.y,h1,l1); split2(v.z,h2,l2); split2(v.w,h3,l3);
            int o = r * A_STR + c * 4;
            Ahi[o+0]=h0; Ahi[o+1]=h1; Ahi[o+2]=h2; Ahi[o+3]=h3;
            Alo[o+0]=l0; Alo[o+1]=l1; Alo[o+2]=l2; Alo[o+3]=l3;
        }
        // ---- B chunk: 32 k x 128 n (fp32) -> hi/lo bf16, layout [k][n] ----
        #pragma unroll
        for (int i = 0; i < 4; i++) {
            int idx = i * 256 + t;            // 0..1023 float4s
            int kr = idx >> 5, c = idx & 31;  // 32 float4 per k-row
            float4 v = *reinterpret_cast<const float4*>(
                &W[(size_t)(k0 + kr) * DD + n0 + c * 4]);
            __nv_bfloat16 h0,h1,h2,h3,l0,l1,l2,l3;
            split2(v.x,h0,l0); split2(v.y,h1,l1); split2(v.z,h2,l2); split2(v.w,h3,l3);
            int o = kr * B_STR + c * 4;
            Bhi[o+0]=h0; Bhi[o+1]=h1; Bhi[o+2]=h2; Bhi[o+3]=h3;
            Blo[o+0]=l0; Blo[o+1]=l1; Blo[o+2]=l2; Blo[o+3]=l3;
        }
        __syncthreads();

        #pragma unroll
        for (int ks = 0; ks < KC; ks += 16) {
            wmma::fragment<wmma::matrix_a, 16, 16, 16, __nv_bfloat16, wmma::row_major> ah[4], al[4];
            wmma::fragment<wmma::matrix_b, 16, 16, 16, __nv_bfloat16, wmma::row_major> bh[2], bl[2];
            #pragma unroll
            for (int i = 0; i < 4; i++) {
                const __nv_bfloat16* pa = Ahi + (warp_m * 64 + i * 16) * A_STR + ks;
                const __nv_bfloat16* qa = Alo + (warp_m * 64 + i * 16) * A_STR + ks;
                wmma::load_matrix_sync(ah[i], pa, A_STR);
                wmma::load_matrix_sync(al[i], qa, A_STR);
            }
            #pragma unroll
            for (int j = 0; j < 2; j++) {
                const __nv_bfloat16* pb = Bhi + ks * B_STR + warp_n * 32 + j * 16;
                const __nv_bfloat16* qb = Blo + ks * B_STR + warp_n * 32 + j * 16;
                wmma::load_matrix_sync(bh[j], pb, B_STR);
                wmma::load_matrix_sync(bl[j], qb, B_STR);
            }
            #pragma unroll
            for (int i = 0; i < 4; i++)
                #pragma unroll
                for (int j = 0; j < 2; j++) {
                    wmma::mma_sync(acc[i][j], ah[i], bh[j], acc[i][j]);
                    wmma::mma_sync(acc[i][j], ah[i], bl[j], acc[i][j]);
                    wmma::mma_sync(acc[i][j], al[i], bh[j], acc[i][j]);
                }
        }
    }

    // ---- epilogue: direct fragment stores to global ----
    float* dst = (mode == 0) ? g_q : (mode == 1) ? g_k : (mode == 2) ? g_v : Cout;
    #pragma unroll
    for (int i = 0; i < 4; i++) {
        #pragma unroll
        for (int j = 0; j < 2; j++) {
            int row0 = rowBase + warp_m * 64 + i * 16;
            int col0 = n0 + warp_n * 32 + j * 16;
            if (mode <= 2) {
                int b = row0 >> 10, s = row0 & 1023;
                int h = col0 >> 6,  d = col0 & 63;
                wmma::store_matrix_sync(&dst[(((size_t)(b * HH + h) * SS + s) * HD) + d],
                                        acc[i][j], HD, wmma::mem_row_major);
            } else {
                wmma::store_matrix_sync(&dst[(size_t)row0 * DD + col0],
                                        acc[i][j], DD, wmma::mem_row_major);
            }
        }
    }
}

// ---------------- goal bias ----------------
__global__ void goalbias_kernel(const float* __restrict__ gs,
                                const float* __restrict__ Wg,
                                const float* __restrict__ bg)
{
    int h = blockIdx.x, b = blockIdx.y;
    int t = threadIdx.x;
    float sum = 0.f;
    for (int k = t; k < DD; k += 256)
        sum += gs[b * DD + k] * Wg[k * HH + h];
    __shared__ float red[256];
    red[t] = sum; __syncthreads();
    for (int o = 128; o > 0; o >>= 1) {
        if (t < o) red[t] += red[t + o];
        __syncthreads();
    }
    if (t == 0) g_bias[b * HH + h] = red[0] + bg[h];
}

// ---------------- fused flash attention (two-pass, exact softmax) ----------------
__global__ __launch_bounds__(256) void flash_kernel(float* __restrict__ attn)
{
    const int qt = blockIdx.x, bh = blockIdx.y;
    extern __shared__ float sm[];
    float* Qs = sm;
    float* KV = sm + 64 * 68;
    float* Ps = sm + 2 * 64 * 68;

    const int t = threadIdx.x;
    const int tx = t & 15, ty = t >> 4;
    const float* Qg = g_q + ((size_t)bh * SS + qt * 64) * HD;
    const float* Kg = g_k + (size_t)bh * SS * HD;
    const float* Vg = g_v + (size_t)bh * SS * HD;
    const float bias = g_bias[bh];
    const float scale = 0.125f;

    #pragma unroll
    for (int i = 0; i < 4; i++) {
        int idx = t + i * 256;
        int r   = idx >> 4;
        int dc  = (idx & 15) * 4;
        float4 v = *reinterpret_cast<const float4*>(&Qg[r * HD + dc]);
        Qs[(dc+0)*68 + r] = v.x; Qs[(dc+1)*68 + r] = v.y;
        Qs[(dc+2)*68 + r] = v.z; Qs[(dc+3)*68 + r] = v.w;
    }

    float M[4], L[4];
    #pragma unroll
    for (int i = 0; i < 4; i++) { M[i] = -1e30f; L[i] = 0.f; }

    for (int kt = 0; kt <= qt; kt++) {
        __syncthreads();
        #pragma unroll
        for (int i = 0; i < 4; i++) {
            int idx = t + i * 256;
            int r   = idx >> 4;
            int dc  = (idx & 15) * 4;
            float4 v = *reinterpret_cast<const float4*>(&Kg[(kt * 64 + r) * HD + dc]);
            KV[(dc+0)*68 + r] = v.x; KV[(dc+1)*68 + r] = v.y;
            KV[(dc+2)*68 + r] = v.z; KV[(dc+3)*68 + r] = v.w;
        }
        __syncthreads();

        float s[4][4];
        #pragma unroll
        for (int i = 0; i < 4; i++)
            #pragma unroll
            for (int j = 0; j < 4; j++) s[i][j] = 0.f;
        #pragma unroll 8
        for (int d = 0; d < 64; d++) {
            float4 a = *reinterpret_cast<float4*>(&Qs[d*68 + ty*4]);
            float4 b = *reinterpret_cast<float4*>(&KV[d*68 + tx*4]);
            float ra[4] = {a.x, a.y, a.z, a.w};
            float rb[4] = {b.x, b.y, b.z, b.w};
            #pragma unroll
            for (int i = 0; i < 4; i++)
                #pragma unroll
                for (int j = 0; j < 4; j++)
                    s[i][j] += ra[i] * rb[j];
        }
        #pragma unroll
        for (int i = 0; i < 4; i++) {
            int qrow = qt * 64 + ty * 4 + i;
            #pragma unroll
            for (int j = 0; j < 4; j++) {
                int kcol = kt * 64 + tx * 4 + j;
                float v = s[i][j] * scale + bias;
                s[i][j] = (kcol > qrow) ? -1e30f : v;
            }
            float m = fmaxf(fmaxf(s[i][0], s[i][1]), fmaxf(s[i][2], s[i][3]));
            #pragma unroll
            for (int o = 1; o < 16; o <<= 1)
                m = fmaxf(m, __shfl_xor_sync(0xffffffffu, m, o));
            float Mn = fmaxf(M[i], m);
            float l = expf(s[i][0]-Mn) + expf(s[i][1]-Mn) + expf(s[i][2]-Mn) + expf(s[i][3]-Mn);
            #pragma unroll
            for (int o = 1; o < 16; o <<= 1)
                l += __shfl_xor_sync(0xffffffffu, l, o);
            L[i] = L[i] * expf(M[i] - Mn) + l;
            M[i] = Mn;
        }
    }

    float invL[4];
    #pragma unroll
    for (int i = 0; i < 4; i++) invL[i] = 1.0f / L[i];

    float acc[4][4];
    #pragma unroll
    for (int i = 0; i < 4; i++)
        #pragma unroll
        for (int j = 0; j < 4; j++) acc[i][j] = 0.f;

    for (int kt = 0; kt <= qt; kt++) {
        __syncthreads();
        #pragma unroll
        for (int i = 0; i < 4; i++) {
            int idx = t + i * 256;
            int r   = idx >> 4;
            int dc  = (idx & 15) * 4;
            float4 v = *reinterpret_cast<const float4*>(&Kg[(kt * 64 + r) * HD + dc]);
            KV[(dc+0)*68 + r] = v.x; KV[(dc+1)*68 + r] = v.y;
            KV[(dc+2)*68 + r] = v.z; KV[(dc+3)*68 + r] = v.w;
        }
        __syncthreads();

        float s[4][4];
        #pragma unroll
        for (int i = 0; i < 4; i++)
            #pragma unroll
            for (int j = 0; j < 4; j++) s[i][j] = 0.f;
        #pragma unroll 8
        for (int d = 0; d < 64; d++) {
            float4 a = *reinterpret_cast<float4*>(&Qs[d*68 + ty*4]);
            float4 b = *reinterpret_cast<float4*>(&KV[d*68 + tx*4]);
            float ra[4] = {a.x, a.y, a.z, a.w};
            float rb[4] = {b.x, b.y, b.z, b.w};
            #pragma unroll
            for (int i = 0; i < 4; i++)
                #pragma unroll
                for (int j = 0; j < 4; j++)
                    s[i][j] += ra[i] * rb[j];
        }
        float p[4][4];
        #pragma unroll
        for (int i = 0; i < 4; i++) {
            int qrow = qt * 64 + ty * 4 + i;
            #pragma unroll
            for (int j = 0; j < 4; j++) {
                int kcol = kt * 64 + tx * 4 + j;
                float v = s[i][j] * scale + bias;
                v = (kcol > qrow) ? -1e30f : v;
                p[i][j] = expf(v - M[i]) * invL[i];
            }
        }
        if (attn) {
            #pragma unroll
            for (int i = 0; i < 4; i++) {
                float4 pv = make_float4(p[i][0], p[i][1], p[i][2], p[i][3]);
                *reinterpret_cast<float4*>(
                    &attn[(size_t)bh * SS * SS + (size_t)(qt*64 + ty*4 + i) * SS + kt*64 + tx*4]) = pv;
            }
        }
        __syncthreads();
        #pragma unroll
        for (int i = 0; i < 4; i++)
            #pragma unroll
            for (int j = 0; j < 4; j++)
                Ps[(tx*4+j)*68 + ty*4+i] = p[i][j];
        #pragma unroll
        for (int i = 0; i < 4; i++) {
            int idx = t + i * 256;
            int r   = idx >> 4;
            int dc  = (idx & 15) * 4;
            *reinterpret_cast<float4*>(&KV[r*68 + dc]) =
                *reinterpret_cast<const float4*>(&Vg[(kt * 64 + r) * HD + dc]);
        }
        __syncthreads();
        #pragma unroll 8
        for (int kk = 0; kk < 64; kk++) {
            float4 a = *reinterpret_cast<float4*>(&Ps[kk*68 + ty*4]);
            float4 b = *reinterpret_cast<float4*>(&KV[kk*68 + tx*4]);
            float ra[4] = {a.x, a.y, a.z, a.w};
            float rb[4] = {b.x, b.y, b.z, b.w};
            #pragma unroll
            for (int i = 0; i < 4; i++)
                #pragma unroll
                for (int j = 0; j < 4; j++)
                    acc[i][j] += ra[i] * rb[j];
        }
    }

    const int b = bh >> 4, h = bh & 15;
    #pragma unroll
    for (int i = 0; i < 4; i++) {
        int srow = qt * 64 + ty * 4 + i;
        float4 cv = make_float4(acc[i][0], acc[i][1], acc[i][2], acc[i][3]);
        *reinterpret_cast<float4*>(
            &g_ctx[((size_t)(b * SS + srow)) * DD + h * 64 + tx * 4]) = cv;
    }

    if (attn && qt < 15) {
        const int c0 = (qt + 1) * 64;
        const int w4 = (SS - c0) >> 2;
        const float4 z4 = make_float4(0.f, 0.f, 0.f, 0.f);
        for (int idx = t; idx < 64 * w4; idx += 256) {
            int r = idx / w4, c = idx % w4;
            *reinterpret_cast<float4*>(
                &attn[(size_t)bh * SS * SS + (size_t)(qt*64 + r) * SS + c0 + c*4]) = z4;
        }
    }
}

// ---------------- launch ----------------
extern "C" void kernel_launch(void* const* d_in, const int* in_sizes, int n_in,
                              void* d_out, int out_size)
{
    const float *query, *key, *value, *goal_state;
    const float *Wq, *bq, *Wk, *bk, *Wv, *bv, *Wo, *bo, *Wg, *bg;

    if (in_sizes[0] == DD * HH) {
        Wg = (const float*)d_in[0];
        Wk = (const float*)d_in[1];
        Wo = (const float*)d_in[2];
        Wq = (const float*)d_in[3];
        Wv = (const float*)d_in[4];
        bg = (const float*)d_in[6];
        bk = (const float*)d_in[7];
        bo = (const float*)d_in[8];
        bq = (const float*)d_in[9];
        bv = (const float*)d_in[10];
        goal_state = (const float*)d_in[11];
        key   = (const float*)d_in[12];
        query = (const float*)d_in[13];
        value = (const float*)d_in[14];
    } else {
        int wb = -1;
        for (int i = 0; i + 9 < n_in; i++) {
            if (in_sizes[i]     == 1048576 && in_sizes[i + 1] == 1024 &&
                in_sizes[i + 2] == 1048576 && in_sizes[i + 3] == 1024 &&
                in_sizes[i + 4] == 1048576 && in_sizes[i + 5] == 1024 &&
                in_sizes[i + 6] == 1048576 && in_sizes[i + 7] == 1024 &&
                in_sizes[i + 8] == 16384   && in_sizes[i + 9] == 16) {
                wb = i;
                break;
            }
        }
        if (wb < 0) wb = n_in - 10;
        Wq = (const float*)d_in[wb + 0];
        bq = (const float*)d_in[wb + 1];
        Wk = (const float*)d_in[wb + 2];
        bk = (const float*)d_in[wb + 3];
        Wv = (const float*)d_in[wb + 4];
        bv = (const float*)d_in[wb + 5];
        Wo = (const float*)d_in[wb + 6];
        bo = (const float*)d_in[wb + 7];
        Wg = (const float*)d_in[wb + 8];
        bg = (const float*)d_in[wb + 9];

        int qi = -1, ki = -1, vi = -1, gi = -1;
        for (int i = 0; i < n_in; i++) {
            if (i >= wb && i < wb + 10) continue;
            if (in_sizes[i] == BB * SS * DD) {
                if (qi < 0) qi = i;
                else if (ki < 0) ki = i;
                else if (vi < 0) vi = i;
            } else if (in_sizes[i] == BB * DD && gi < 0) {
                gi = i;
            }
        }
        query      = (const float*)d_in[qi < 0 ? 0 : qi];
        key        = (const float*)d_in[ki < 0 ? 1 : ki];
        value      = (const float*)d_in[vi < 0 ? 2 : vi];
        goal_state = (const float*)d_in[gi < 0 ? 3 : gi];
    }

    float* out = (float*)d_out;
    const size_t out_elems  = (size_t)BB * SS * DD;
    const size_t attn_elems = (size_t)BB * HH * SS * SS;
    float* attn = ((size_t)out_size >= out_elems + attn_elems) ? (out + out_elems) : nullptr;

    cudaFuncSetAttribute(proj_wmma_kernel, cudaFuncAttributeMaxDynamicSharedMemorySize, SM_TOT);

    dim3 projGrid(DD / 128, (BB * SS) / 128);   // (8, 32)
    proj_wmma_kernel<<<projGrid, 256, SM_TOT>>>(query, Wq, bq, nullptr, 0);
    proj_wmma_kernel<<<projGrid, 256, SM_TOT>>>(key,   Wk, bk, nullptr, 1);
    proj_wmma_kernel<<<projGrid, 256, SM_TOT>>>(value, Wv, bv, nullptr, 2);

    goalbias_kernel<<<dim3(HH, BB), 256>>>(goal_state, Wg, bg);

    const int flash_smem = 3 * 64 * 68 * (int)sizeof(float);
    cudaFuncSetAttribute(flash_kernel, cudaFuncAttributeMaxDynamicSharedMemorySize, flash_smem);
    flash_kernel<<<dim3(SS / 64, BB * HH), 256, flash_smem>>>(attn);

    // mode 3: A resolved in device code (g_ctx); first arg is a dummy.
    proj_wmma_kernel<<<projGrid, 256, SM_TOT>>>(out, Wo, bo, out, 3);
}

// round 17
// speedup vs baseline: 1.3626x; 1.0658x over previous
#include <cuda_runtime.h>
#include <cuda_bf16.h>
#include <mma.h>
#include <math.h>
#include <stdint.h>

using namespace nvcuda;

#define BB 4
#define SS 1024
#define DD 1024
#define HH 16
#define HD 64

// ---------------- static scratch ----------------
__device__ float g_q[BB*HH*SS*HD];     // [B,H,S,HD]
__device__ float g_k[BB*HH*SS*HD];
__device__ float g_v[BB*HH*SS*HD];
__device__ float g_ctx[BB*SS*DD];      // [B,S,D]
__device__ float g_bias[BB*HH];

// bf16 hi/lo pre-converted operands
// act slots: 0=query 1=key 2=value 3=ctx   (each 4,194,304 elems)
// w   slots: 0=Wq 1=Wk 2=Wv 3=Wo           (each 1,048,576 elems)
#define ACT_N 4194304
#define W_N   1048576
__device__ __nv_bfloat16 g_act_hi[4 * ACT_N];
__device__ __nv_bfloat16 g_act_lo[4 * ACT_N];
__device__ __nv_bfloat16 g_w_hi[4 * W_N];
__device__ __nv_bfloat16 g_w_lo[4 * W_N];

// ---------------- cp.async helpers (sm_80 baseline PTX) ----------------
__device__ __forceinline__ uint32_t smem_u32(const void* p) {
    uint32_t a;
    asm("{ .reg .u64 t; cvta.to.shared.u64 t, %1; cvt.u32.u64 %0, t; }" : "=r"(a) : "l"(p));
    return a;
}
__device__ __forceinline__ void cp_async16(uint32_t saddr, const void* g) {
    asm volatile("cp.async.cg.shared.global [%0], [%1], 16;" :: "r"(saddr), "l"(g));
}
__device__ __forceinline__ void cp_commit() {
    asm volatile("cp.async.commit_group;" ::: "memory");
}
template<int N> __device__ __forceinline__ void cp_wait() {
    asm volatile("cp.async.wait_group %0;" :: "n"(N) : "memory");
}

// ---------------- convert: fp32 -> bf16 hi/lo ----------------
// src == nullptr -> read g_ctx (device-side symbol; NEVER pass __device__ syms from host)
__global__ __launch_bounds__(256) void convert_kernel(const float* __restrict__ src,
                                                      int slot, int is_w)
{
    const float* s = src ? src : (const float*)g_ctx;
    __nv_bfloat16* hi = is_w ? (g_w_hi + (size_t)slot * W_N) : (g_act_hi + (size_t)slot * ACT_N);
    __nv_bfloat16* lo = is_w ? (g_w_lo + (size_t)slot * W_N) : (g_act_lo + (size_t)slot * ACT_N);
    int idx = blockIdx.x * 256 + threadIdx.x;        // one float4 per thread
    float4 v = *reinterpret_cast<const float4*>(&s[(size_t)idx * 4]);
    __nv_bfloat16 h0 = __float2bfloat16_rn(v.x);
    __nv_bfloat16 h1 = __float2bfloat16_rn(v.y);
    __nv_bfloat16 h2 = __float2bfloat16_rn(v.z);
    __nv_bfloat16 h3 = __float2bfloat16_rn(v.w);
    __nv_bfloat16 l0 = __float2bfloat16_rn(v.x - __bfloat162float(h0));
    __nv_bfloat16 l1 = __float2bfloat16_rn(v.y - __bfloat162float(h1));
    __nv_bfloat16 l2 = __float2bfloat16_rn(v.z - __bfloat162float(h2));
    __nv_bfloat16 l3 = __float2bfloat16_rn(v.w - __bfloat162float(h3));
    uint2 ph, pl;
    ph.x = ((uint32_t)__bfloat16_as_ushort(h1) << 16) | __bfloat16_as_ushort(h0);
    ph.y = ((uint32_t)__bfloat16_as_ushort(h3) << 16) | __bfloat16_as_ushort(h2);
    pl.x = ((uint32_t)__bfloat16_as_ushort(l1) << 16) | __bfloat16_as_ushort(l0);
    pl.y = ((uint32_t)__bfloat16_as_ushort(l3) << 16) | __bfloat16_as_ushort(l2);
    *reinterpret_cast<uint2*>(&hi[(size_t)idx * 4]) = ph;
    *reinterpret_cast<uint2*>(&lo[(size_t)idx * 4]) = pl;
}

// ============ wmma bf16 split-3 projection GEMM (pre-converted operands) ============
// CTA tile 128(M) x 128(N), 8 warps (2x4), warp tile 64x32. KC=32, double-buffered cp.async.
// grid (8, 32, Z): slot = base_slot + z. mode<=2: write g_q/g_k/g_v; mode 3: Cout row-major.
#define KC 32
#define A_STR 40     // bf16/row (80 B, 16B-aligned)
#define B_STR 136    // bf16/row (272 B, 16B-aligned)

#define STG_A  (128 * A_STR * 2)              // 10240 B per A matrix
#define STG_B  (KC * B_STR * 2)               // 8704 B per B matrix
#define STG_SZ (2 * STG_A + 2 * STG_B)        // 37888 B per stage (Ahi,Alo,Bhi,Blo)
#define SBIAS  (2 * STG_SZ)                   // 75776
#define SM_TOT (SBIAS + 16 * B_STR * 4)       // 84480 B

__global__ __launch_bounds__(256) void proj_wmma_kernel(
    const float* __restrict__ bias0, const float* __restrict__ bias1,
    const float* __restrict__ bias2, float* __restrict__ Cout, int base_slot)
{
    extern __shared__ char smem[];
    const int z = blockIdx.z;
    const int slot = base_slot + z;                 // act + w slot
    const int mode = (base_slot == 3) ? 3 : z;      // 0/1/2 -> q/k/v, 3 -> out
    const float* bias = (z == 0) ? bias0 : (z == 1) ? bias1 : bias2;

    const __nv_bfloat16* Ahg = g_act_hi + (size_t)slot * ACT_N;
    const __nv_bfloat16* Alg = g_act_lo + (size_t)slot * ACT_N;
    const __nv_bfloat16* Bhg = g_w_hi + (size_t)slot * W_N;
    const __nv_bfloat16* Blg = g_w_lo + (size_t)slot * W_N;

    const int t = threadIdx.x;
    const int wid = t >> 5;
    const int warp_m = wid >> 2;      // 0..1
    const int warp_n = wid & 3;       // 0..3
    const int n0 = blockIdx.x * 128;
    const int rowBase = blockIdx.y * 128;

    float* biasC = (float*)(smem + SBIAS);
    for (int idx = t; idx < 16 * 128; idx += 256) {
        int r = idx >> 7, c = idx & 127;
        biasC[r * B_STR + c] = bias[n0 + c];
    }

    // prefetch helper: chunk k-index kc into stage s
    auto prefetch = [&](int kc, int s) {
        char* stg = smem + s * STG_SZ;
        uint32_t sAhi = smem_u32(stg);
        uint32_t sAlo = smem_u32(stg + STG_A);
        uint32_t sBhi = smem_u32(stg + 2 * STG_A);
        uint32_t sBlo = smem_u32(stg + 2 * STG_A + STG_B);
        const int k0 = kc * KC;
        // A: 128 rows x 32 k -> 4 uint4/row, 512 per matrix
        #pragma unroll
        for (int i = 0; i < 2; i++) {
            int idx = i * 256 + t;          // 0..511
            int r = idx >> 2, c = idx & 3;  // c: uint4 within row
            size_t go = (size_t)(rowBase + r) * DD + k0 + c * 8;
            uint32_t so = (uint32_t)(r * A_STR + c * 8) * 2;
            cp_async16(sAhi + so, Ahg + go);
            cp_async16(sAlo + so, Alg + go);
        }
        // B: 32 k-rows x 128 n -> 16 uint4/row, 512 per matrix
        #pragma unroll
        for (int i = 0; i < 2; i++) {
            int idx = i * 256 + t;
            int kr = idx >> 4, c = idx & 15;
            size_t go = (size_t)(k0 + kr) * DD + n0 + c * 8;
            uint32_t so = (uint32_t)(kr * B_STR + c * 8) * 2;
            cp_async16(sBhi + so, Bhg + go);
            cp_async16(sBlo + so, Blg + go);
        }
        cp_commit();
    };

    prefetch(0, 0);
    __syncthreads();   // biasC ready

    wmma::fragment<wmma::accumulator, 16, 16, 16, float> acc[4][2];
    #pragma unroll
    for (int i = 0; i < 4; i++)
        #pragma unroll
        for (int j = 0; j < 2; j++)
            wmma::load_matrix_sync(acc[i][j], biasC + warp_n * 32 + j * 16,
                                   B_STR, wmma::mem_row_major);

    const int NCH = DD / KC;   // 32
    for (int i = 0; i < NCH; i++) {
        __syncthreads();                      // everyone done with stage (i-1)&1
        if (i + 1 < NCH) {
            prefetch(i + 1, (i + 1) & 1);
            cp_wait<1>();
        } else {
            cp_wait<0>();
        }
        __syncthreads();                      // stage i&1 data visible to all

        char* stg = smem + (i & 1) * STG_SZ;
        __nv_bfloat16* Ahi = (__nv_bfloat16*)stg;
        __nv_bfloat16* Alo = (__nv_bfloat16*)(stg + STG_A);
        __nv_bfloat16* Bhi = (__nv_bfloat16*)(stg + 2 * STG_A);
        __nv_bfloat16* Blo = (__nv_bfloat16*)(stg + 2 * STG_A + STG_B);

        #pragma unroll
        for (int ks = 0; ks < KC; ks += 16) {
            wmma::fragment<wmma::matrix_a, 16, 16, 16, __nv_bfloat16, wmma::row_major> ah[4], al[4];
            wmma::fragment<wmma::matrix_b, 16, 16, 16, __nv_bfloat16, wmma::row_major> bh[2], bl[2];
            #pragma unroll
            for (int ii = 0; ii < 4; ii++) {
                wmma::load_matrix_sync(ah[ii], Ahi + (warp_m * 64 + ii * 16) * A_STR + ks, A_STR);
                wmma::load_matrix_sync(al[ii], Alo + (warp_m * 64 + ii * 16) * A_STR + ks, A_STR);
            }
            #pragma unroll
            for (int j = 0; j < 2; j++) {
                wmma::load_matrix_sync(bh[j], Bhi + ks * B_STR + warp_n * 32 + j * 16, B_STR);
                wmma::load_matrix_sync(bl[j], Blo + ks * B_STR + warp_n * 32 + j * 16, B_STR);
            }
            #pragma unroll
            for (int ii = 0; ii < 4; ii++)
                #pragma unroll
                for (int j = 0; j < 2; j++) {
                    wmma::mma_sync(acc[ii][j], ah[ii], bh[j], acc[ii][j]);
                    wmma::mma_sync(acc[ii][j], ah[ii], bl[j], acc[ii][j]);
                    wmma::mma_sync(acc[ii][j], al[ii], bh[j], acc[ii][j]);
                }
        }
    }

    // ---- epilogue: direct fragment stores to global ----
    float* dst = (mode == 0) ? g_q : (mode == 1) ? g_k : (mode == 2) ? g_v : Cout;
    #pragma unroll
    for (int i = 0; i < 4; i++) {
        #pragma unroll
        for (int j = 0; j < 2; j++) {
            int row0 = rowBase + warp_m * 64 + i * 16;
            int col0 = n0 + warp_n * 32 + j * 16;
            if (mode <= 2) {
                int b = row0 >> 10, s = row0 & 1023;
                int h = col0 >> 6,  d = col0 & 63;
                wmma::store_matrix_sync(&dst[(((size_t)(b * HH + h) * SS + s) * HD) + d],
                                        acc[i][j], HD, wmma::mem_row_major);
            } else {
                wmma::store_matrix_sync(&dst[(size_t)row0 * DD + col0],
                                        acc[i][j], DD, wmma::mem_row_major);
            }
        }
    }
}

// ---------------- goal bias ----------------
__global__ void goalbias_kernel(const float* __restrict__ gs,
                                const float* __restrict__ Wg,
                                const float* __restrict__ bg)
{
    int h = blockIdx.x, b = blockIdx.y;
    int t = threadIdx.x;
    float sum = 0.f;
    for (int k = t; k < DD; k += 256)
        sum += gs[b * DD + k] * Wg[k * HH + h];
    __shared__ float red[256];
    red[t] = sum; __syncthreads();
    for (int o = 128; o > 0; o >>= 1) {
        if (t < o) red[t] += red[t + o];
        __syncthreads();
    }
    if (t == 0) g_bias[b * HH + h] = red[0] + bg[h];
}

// ---------------- fused flash attention (two-pass, exact softmax) ----------------
__global__ __launch_bounds__(256) void flash_kernel(float* __restrict__ attn)
{
    const int qt = blockIdx.x, bh = blockIdx.y;
    extern __shared__ float sm[];
    float* Qs = sm;
    float* KV = sm + 64 * 68;
    float* Ps = sm + 2 * 64 * 68;

    const int t = threadIdx.x;
    const int tx = t & 15, ty = t >> 4;
    const float* Qg = g_q + ((size_t)bh * SS + qt * 64) * HD;
    const float* Kg = g_k + (size_t)bh * SS * HD;
    const float* Vg = g_v + (size_t)bh * SS * HD;
    const float bias = g_bias[bh];
    const float scale = 0.125f;

    #pragma unroll
    for (int i = 0; i < 4; i++) {
        int idx = t + i * 256;
        int r   = idx >> 4;
        int dc  = (idx & 15) * 4;
        float4 v = *reinterpret_cast<const float4*>(&Qg[r * HD + dc]);
        Qs[(dc+0)*68 + r] = v.x; Qs[(dc+1)*68 + r] = v.y;
        Qs[(dc+2)*68 + r] = v.z; Qs[(dc+3)*68 + r] = v.w;
    }

    float M[4], L[4];
    #pragma unroll
    for (int i = 0; i < 4; i++) { M[i] = -1e30f; L[i] = 0.f; }

    for (int kt = 0; kt <= qt; kt++) {
        __syncthreads();
        #pragma unroll
        for (int i = 0; i < 4; i++) {
            int idx = t + i * 256;
            int r   = idx >> 4;
            int dc  = (idx & 15) * 4;
            float4 v = *reinterpret_cast<const float4*>(&Kg[(kt * 64 + r) * HD + dc]);
            KV[(dc+0)*68 + r] = v.x; KV[(dc+1)*68 + r] = v.y;
            KV[(dc+2)*68 + r] = v.z; KV[(dc+3)*68 + r] = v.w;
        }
        __syncthreads();

        float s[4][4];
        #pragma unroll
        for (int i = 0; i < 4; i++)
            #pragma unroll
            for (int j = 0; j < 4; j++) s[i][j] = 0.f;
        #pragma unroll 8
        for (int d = 0; d < 64; d++) {
            float4 a = *reinterpret_cast<float4*>(&Qs[d*68 + ty*4]);
            float4 b = *reinterpret_cast<float4*>(&KV[d*68 + tx*4]);
            float ra[4] = {a.x, a.y, a.z, a.w};
            float rb[4] = {b.x, b.y, b.z, b.w};
            #pragma unroll
            for (int i = 0; i < 4; i++)
                #pragma unroll
                for (int j = 0; j < 4; j++)
                    s[i][j] += ra[i] * rb[j];
        }
        #pragma unroll
        for (int i = 0; i < 4; i++) {
            int qrow = qt * 64 + ty * 4 + i;
            #pragma unroll
            for (int j = 0; j < 4; j++) {
                int kcol = kt * 64 + tx * 4 + j;
                float v = s[i][j] * scale + bias;
                s[i][j] = (kcol > qrow) ? -1e30f : v;
            }
            float m = fmaxf(fmaxf(s[i][0], s[i][1]), fmaxf(s[i][2], s[i][3]));
            #pragma unroll
            for (int o = 1; o < 16; o <<= 1)
                m = fmaxf(m, __shfl_xor_sync(0xffffffffu, m, o));
            float Mn = fmaxf(M[i], m);
            float l = expf(s[i][0]-Mn) + expf(s[i][1]-Mn) + expf(s[i][2]-Mn) + expf(s[i][3]-Mn);
            #pragma unroll
            for (int o = 1; o < 16; o <<= 1)
                l += __shfl_xor_sync(0xffffffffu, l, o);
            L[i] = L[i] * expf(M[i] - Mn) + l;
            M[i] = Mn;
        }
    }

    float invL[4];
    #pragma unroll
    for (int i = 0; i < 4; i++) invL[i] = 1.0f / L[i];

    float acc[4][4];
    #pragma unroll
    for (int i = 0; i < 4; i++)
        #pragma unroll
        for (int j = 0; j < 4; j++) acc[i][j] = 0.f;

    for (int kt = 0; kt <= qt; kt++) {
        __syncthreads();
        #pragma unroll
        for (int i = 0; i < 4; i++) {
            int idx = t + i * 256;
            int r   = idx >> 4;
            int dc  = (idx & 15) * 4;
            float4 v = *reinterpret_cast<const float4*>(&Kg[(kt * 64 + r) * HD + dc]);
            KV[(dc+0)*68 + r] = v.x; KV[(dc+1)*68 + r] = v.y;
            KV[(dc+2)*68 + r] = v.z; KV[(dc+3)*68 + r] = v.w;
        }
        __syncthreads();

        float s[4][4];
        #pragma unroll
        for (int i = 0; i < 4; i++)
            #pragma unroll
            for (int j = 0; j < 4; j++) s[i][j] = 0.f;
        #pragma unroll 8
        for (int d = 0; d < 64; d++) {
            float4 a = *reinterpret_cast<float4*>(&Qs[d*68 + ty*4]);
            float4 b = *reinterpret_cast<float4*>(&KV[d*68 + tx*4]);
            float ra[4] = {a.x, a.y, a.z, a.w};
            float rb[4] = {b.x, b.y, b.z, b.w};
            #pragma unroll
            for (int i = 0; i < 4; i++)
                #pragma unroll
                for (int j = 0; j < 4; j++)
                    s[i][j] += ra[i] * rb[j];
        }
        float p[4][4];
        #pragma unroll
        for (int i = 0; i < 4; i++) {
            int qrow = qt * 64 + ty * 4 + i;
            #pragma unroll
            for (int j = 0; j < 4; j++) {
                int kcol = kt * 64 + tx * 4 + j;
                float v = s[i][j] * scale + bias;
                v = (kcol > qrow) ? -1e30f : v;
                p[i][j] = expf(v - M[i]) * invL[i];
            }
        }
        if (attn) {
            #pragma unroll
            for (int i = 0; i < 4; i++) {
                float4 pv = make_float4(p[i][0], p[i][1], p[i][2], p[i][3]);
                *reinterpret_cast<float4*>(
                    &attn[(size_t)bh * SS * SS + (size_t)(qt*64 + ty*4 + i) * SS + kt*64 + tx*4]) = pv;
            }
        }
        __syncthreads();
        #pragma unroll
        for (int i = 0; i < 4; i++)
            #pragma unroll
            for (int j = 0; j < 4; j++)
                Ps[(tx*4+j)*68 + ty*4+i] = p[i][j];
        #pragma unroll
        for (int i = 0; i < 4; i++) {
            int idx = t + i * 256;
            int r   = idx >> 4;
            int dc  = (idx & 15) * 4;
            *reinterpret_cast<float4*>(&KV[r*68 + dc]) =
                *reinterpret_cast<const float4*>(&Vg[(kt * 64 + r) * HD + dc]);
        }
        __syncthreads();
        #pragma unroll 8
        for (int kk = 0; kk < 64; kk++) {
            float4 a = *reinterpret_cast<float4*>(&Ps[kk*68 + ty*4]);
            float4 b = *reinterpret_cast<float4*>(&KV[kk*68 + tx*4]);
            float ra[4] = {a.x, a.y, a.z, a.w};
            float rb[4] = {b.x, b.y, b.z, b.w};
            #pragma unroll
            for (int i = 0; i < 4; i++)
                #pragma unroll
                for (int j = 0; j < 4; j++)
                    acc[i][j] += ra[i] * rb[j];
        }
    }

    const int b = bh >> 4, h = bh & 15;
    #pragma unroll
    for (int i = 0; i < 4; i++) {
        int srow = qt * 64 + ty * 4 + i;
        float4 cv = make_float4(acc[i][0], acc[i][1], acc[i][2], acc[i][3]);
        *reinterpret_cast<float4*>(
            &g_ctx[((size_t)(b * SS + srow)) * DD + h * 64 + tx * 4]) = cv;
    }

    if (attn && qt < 15) {
        const int c0 = (qt + 1) * 64;
        const int w4 = (SS - c0) >> 2;
        const float4 z4 = make_float4(0.f, 0.f, 0.f, 0.f);
        for (int idx = t; idx < 64 * w4; idx += 256) {
            int r = idx / w4, c = idx % w4;
            *reinterpret_cast<float4*>(
                &attn[(size_t)bh * SS * SS + (size_t)(qt*64 + r) * SS + c0 + c*4]) = z4;
        }
    }
}

// ---------------- launch ----------------
extern "C" void kernel_launch(void* const* d_in, const int* in_sizes, int n_in,
                              void* d_out, int out_size)
{
    const float *query, *key, *value, *goal_state;
    const float *Wq, *bq, *Wk, *bk, *Wv, *bv, *Wo, *bo, *Wg, *bg;

    if (in_sizes[0] == DD * HH) {
        Wg = (const float*)d_in[0];
        Wk = (const float*)d_in[1];
        Wo = (const float*)d_in[2];
        Wq = (const float*)d_in[3];
        Wv = (const float*)d_in[4];
        bg = (const float*)d_in[6];
        bk = (const float*)d_in[7];
        bo = (const float*)d_in[8];
        bq = (const float*)d_in[9];
        bv = (const float*)d_in[10];
        goal_state = (const float*)d_in[11];
        key   = (const float*)d_in[12];
        query = (const float*)d_in[13];
        value = (const float*)d_in[14];
    } else {
        int wb = -1;
        for (int i = 0; i + 9 < n_in; i++) {
            if (in_sizes[i]     == 1048576 && in_sizes[i + 1] == 1024 &&
                in_sizes[i + 2] == 1048576 && in_sizes[i + 3] == 1024 &&
                in_sizes[i + 4] == 1048576 && in_sizes[i + 5] == 1024 &&
                in_sizes[i + 6] == 1048576 && in_sizes[i + 7] == 1024 &&
                in_sizes[i + 8] == 16384   && in_sizes[i + 9] == 16) {
                wb = i;
                break;
            }
        }
        if (wb < 0) wb = n_in - 10;
        Wq = (const float*)d_in[wb + 0];
        bq = (const float*)d_in[wb + 1];
        Wk = (const float*)d_in[wb + 2];
        bk = (const float*)d_in[wb + 3];
        Wv = (const float*)d_in[wb + 4];
        bv = (const float*)d_in[wb + 5];
        Wo = (const float*)d_in[wb + 6];
        bo = (const float*)d_in[wb + 7];
        Wg = (const float*)d_in[wb + 8];
        bg = (const float*)d_in[wb + 9];

        int qi = -1, ki = -1, vi = -1, gi = -1;
        for (int i = 0; i < n_in; i++) {
            if (i >= wb && i < wb + 10) continue;
            if (in_sizes[i] == BB * SS * DD) {
                if (qi < 0) qi = i;
                else if (ki < 0) ki = i;
                else if (vi < 0) vi = i;
            } else if (in_sizes[i] == BB * DD && gi < 0) {
                gi = i;
            }
        }
        query      = (const float*)d_in[qi < 0 ? 0 : qi];
        key        = (const float*)d_in[ki < 0 ? 1 : ki];
        value      = (const float*)d_in[vi < 0 ? 2 : vi];
        goal_state = (const float*)d_in[gi < 0 ? 3 : gi];
    }

    float* out = (float*)d_out;
    const size_t out_elems  = (size_t)BB * SS * DD;
    const size_t attn_elems = (size_t)BB * HH * SS * SS;
    float* attn = ((size_t)out_size >= out_elems + attn_elems) ? (out + out_elems) : nullptr;

    // ---- pre-convert activations + weights to bf16 hi/lo ----
    convert_kernel<<<ACT_N / 1024, 256>>>(query, 0, 0);
    convert_kernel<<<ACT_N / 1024, 256>>>(key,   1, 0);
    convert_kernel<<<ACT_N / 1024, 256>>>(value, 2, 0);
    convert_kernel<<<W_N / 1024, 256>>>(Wq, 0, 1);
    convert_kernel<<<W_N / 1024, 256>>>(Wk, 1, 1);
    convert_kernel<<<W_N / 1024, 256>>>(Wv, 2, 1);
    convert_kernel<<<W_N / 1024, 256>>>(Wo, 3, 1);

    cudaFuncSetAttribute(proj_wmma_kernel, cudaFuncAttributeMaxDynamicSharedMemorySize, SM_TOT);

    // fused Q/K/V projections
    proj_wmma_kernel<<<dim3(8, 32, 3), 256, SM_TOT>>>(bq, bk, bv, nullptr, 0);

    goalbias_kernel<<<dim3(HH, BB), 256>>>(goal_state, Wg, bg);

    const int flash_smem = 3 * 64 * 68 * (int)sizeof(float);
    cudaFuncSetAttribute(flash_kernel, cudaFuncAttributeMaxDynamicSharedMemorySize, flash_smem);
    flash_kernel<<<dim3(SS / 64, BB * HH), 256, flash_smem>>>(attn);

    // convert ctx (device-side g_ctx) then O projection
    convert_kernel<<<ACT_N / 1024, 256>>>(nullptr, 3, 0);
    proj_wmma_kernel<<<dim3(8, 32, 1), 256, SM_TOT>>>(bo, bo, bo, out, 3);
}